// round 8
// baseline (speedup 1.0000x reference)
#include <cuda_runtime.h>
#include <cuda_bf16.h>
#include <math_constants.h>

// Fused greedy CTC decode:
//   index[t] = argmax_v emission[t, v]  (first occurrence on ties)
//   char[t]  = -1 if index==0 ; index-1 if index>1 ; 0 if index==1
//   keep[t]  = (char[t] != char[t-1]) && (char[t] != -1)   (char[-1] := -2)
// Output (float32): [0..T) = (float)index, [T..2T) = keep (0.0/1.0).
//
// 8 warps x 4 rows = 32 rows/block, grid 2048, regs capped to 32
// (__launch_bounds__(256,8)). Two rows per iteration, interleaved at
// float4 granularity: two independent compare chains keep load issue
// continuous across row boundaries. __ldcs (evict-first) for the
// zero-reuse 128MB stream. Warp 0 resolves the block-boundary
// predecessor row; REDUX-based warp argmax.

static constexpr int V = 512;
static constexpr int WARPS = 8;
static constexpr int R = 4;                         // rows per warp
static constexpr int ROWS_PER_BLOCK = WARPS * R;    // 32

// Strictly monotone float -> uint map (order- and equality-preserving).
__device__ __forceinline__ unsigned mono(float f)
{
    unsigned u = __float_as_uint(f);
    return u ^ ((unsigned)((int)u >> 31) | 0x80000000u);
}

__device__ __forceinline__ void cmp4(const float4 v, int e, float& best, int& bidx)
{
    if (v.x > best) { best = v.x; bidx = e;     }
    if (v.y > best) { best = v.y; bidx = e + 1; }
    if (v.z > best) { best = v.z; bidx = e + 2; }
    if (v.w > best) { best = v.w; bidx = e + 3; }
}

// REDUX warp argmax: max value, min index on ties (jnp.argmax semantics).
__device__ __forceinline__ int warp_argmax_reduce(float best, int bidx)
{
    const unsigned k = mono(best);
    const unsigned m = __reduce_max_sync(0xFFFFFFFFu, k);
    const unsigned cand = (k == m) ? (unsigned)bidx : 0x7FFFFFFFu;
    return (int)__reduce_min_sync(0xFFFFFFFFu, cand);
}

// Single-row warp argmax (used only for the block-boundary predecessor).
__device__ __forceinline__ int warp_argmax_row(const float* __restrict__ em,
                                               int row, int lane)
{
    const float4* __restrict__ p =
        reinterpret_cast<const float4*>(em + (size_t)row * V);
    float best = -CUDART_INF_F;
    int   bidx = 0;
#pragma unroll
    for (int c = 0; c < 4; ++c)
        cmp4(__ldcs(p + lane + c * 32), lane * 4 + c * 128, best, bidx);
    return warp_argmax_reduce(best, bidx);
}

__device__ __forceinline__ int ctc_char(int i)
{
    return (i == 0) ? -1 : ((i > 1) ? i - 1 : 0);
}

__global__ __launch_bounds__(WARPS * 32, 8)
void ctc_fused_kernel(const float* __restrict__ em,
                      float* __restrict__ out_index,
                      float* __restrict__ out_keep,
                      int T)
{
    __shared__ int idx_s[ROWS_PER_BLOCK];
    __shared__ int ch[ROWS_PER_BLOCK + 1];   // ch[0] = char of row base-1

    const int warp = threadIdx.x >> 5;
    const int lane = threadIdx.x & 31;
    const int base = blockIdx.x * ROWS_PER_BLOCK;

    // 4 rows per warp, processed two at a time with interleaved float4
    // loads (two independent compare chains; <=4 vectors live at once).
#pragma unroll
    for (int j = 0; j < R; j += 2) {
        const int local0 = warp * R + j;
        const int r0 = base + local0;

        const float4* __restrict__ p0 =
            reinterpret_cast<const float4*>(em + (size_t)r0 * V);
        const float4* __restrict__ p1 =
            reinterpret_cast<const float4*>(em + (size_t)(r0 + 1) * V);

        float best0 = -CUDART_INF_F, best1 = -CUDART_INF_F;
        int   bi0 = 0, bi1 = 0;
#pragma unroll
        for (int c = 0; c < 4; ++c) {
            const float4 a = __ldcs(p0 + lane + c * 32);
            const float4 b = __ldcs(p1 + lane + c * 32);
            const int e = lane * 4 + c * 128;
            cmp4(a, e, best0, bi0);
            cmp4(b, e, best1, bi1);
        }

        const int i0 = warp_argmax_reduce(best0, bi0);
        const int i1 = warp_argmax_reduce(best1, bi1);
        if (lane == 0) {
            idx_s[local0]     = i0;
            idx_s[local0 + 1] = i1;
            ch[1 + local0]     = ctc_char(i0);
            ch[1 + local0 + 1] = ctc_char(i1);
        }
    }

    // Warp 0 resolves the block-boundary predecessor row.
    if (warp == 0) {
        if (base == 0) {
            if (lane == 0) ch[0] = -2;           // char[-1] sentinel
        } else {
            const int bi = warp_argmax_row(em, base - 1, lane);
            if (lane == 0) ch[0] = ctc_char(bi);
        }
    }
    __syncthreads();

    // Coalesced epilogue: first 32 threads write index, next 32 write keep.
    if (threadIdx.x < ROWS_PER_BLOCK) {
        out_index[base + threadIdx.x] = (float)idx_s[threadIdx.x];
    } else if (threadIdx.x < 2 * ROWS_PER_BLOCK) {
        const int l = threadIdx.x - ROWS_PER_BLOCK;
        const int c  = ch[l + 1];
        const int pc = ch[l];
        out_keep[base + l] = (c != pc && c != -1) ? 1.0f : 0.0f;
    }
}

extern "C" void kernel_launch(void* const* d_in, const int* in_sizes, int n_in,
                              void* d_out, int out_size)
{
    const float* em = (const float*)d_in[0];
    const int T = in_sizes[0] / V;           // 65536 (divisible by 32)

    float* out       = (float*)d_out;
    float* out_index = out;
    float* out_keep  = out + T;

    const int grid = T / ROWS_PER_BLOCK;     // 2048
    ctc_fused_kernel<<<grid, WARPS * 32>>>(em, out_index, out_keep, T);
}